// round 1
// baseline (speedup 1.0000x reference)
#include <cuda_runtime.h>

#define D 64
#define MAX_NODES 150016

// Static scratch (allocation-free rule): ping-pong layer buffers + accumulator.
__device__ float g_x[(size_t)MAX_NODES * D];    // layer input
__device__ float g_y[(size_t)MAX_NODES * D];    // layer output
__device__ float g_acc[(size_t)MAX_NODES * D];  // running sum of layer embeddings

// Concatenate user/item embeddings into g_x and g_acc, zero g_y.
__global__ void init_kernel(const float* __restrict__ ue,
                            const float* __restrict__ ie,
                            int n_user_f, int n4) {
    int i = blockIdx.x * blockDim.x + threadIdx.x;   // float4 index
    if (i >= n4) return;
    int f = i << 2;
    float4 v = (f < n_user_f) ? ((const float4*)ue)[i]
                              : ((const float4*)ie)[i - (n_user_f >> 2)];
    ((float4*)g_x)[i]   = v;
    ((float4*)g_acc)[i] = v;
    ((float4*)g_y)[i]   = make_float4(0.f, 0.f, 0.f, 0.f);
}

// SpMM: y[dst] += w * x[src].  16 threads per edge, float4 each (256B/edge,
// fully coalesced gather + vector reduction scatter).
__global__ void spmm_kernel(const int* __restrict__ src,
                            const int* __restrict__ dst,
                            const float* __restrict__ w,
                            int n_edges, int flip) {
    const float* __restrict__ x = flip ? g_y : g_x;
    float* y                    = flip ? g_x : g_y;
    int t = blockIdx.x * blockDim.x + threadIdx.x;
    int e = t >> 4;
    if (e >= n_edges) return;
    int c = (t & 15) << 2;                 // float offset within row: 0..60
    int s  = src[e];
    int dd = dst[e];
    float ww = w[e];
    float4 v = *(const float4*)(x + (size_t)s * D + c);
    float* p = y + (size_t)dd * D + c;
    asm volatile("red.global.add.v4.f32 [%0], {%1,%2,%3,%4};"
                 :: "l"(p), "f"(v.x * ww), "f"(v.y * ww),
                    "f"(v.z * ww), "f"(v.w * ww)
                 : "memory");
}

// acc += y (just-produced layer); clear x (old input) so it can serve as the
// next layer's zeroed output buffer.
__global__ void addclear_kernel(int n4, int flip) {
    float4* y = (float4*)(flip ? g_x : g_y);   // just written by spmm
    float4* x = (float4*)(flip ? g_y : g_x);   // consumed, becomes next y
    int i = blockIdx.x * blockDim.x + threadIdx.x;
    if (i >= n4) return;
    float4 a = ((float4*)g_acc)[i];
    float4 b = y[i];
    a.x += b.x; a.y += b.y; a.z += b.z; a.w += b.w;
    ((float4*)g_acc)[i] = a;
    x[i] = make_float4(0.f, 0.f, 0.f, 0.f);
}

// One warp per (user, item) pair: float2 per lane, shfl reduction.
// Both rows carry an implicit 1/4 scale -> fold 1/16 into the dot product.
__global__ void score_kernel(const int* __restrict__ users,
                             const int* __restrict__ items,
                             float* __restrict__ out, int B, int n_users) {
    int g    = blockIdx.x * blockDim.x + threadIdx.x;
    int pair = g >> 5;
    int lane = threadIdx.x & 31;
    if (pair >= B) return;
    int ur = users[pair];
    int ir = n_users + items[pair];
    float2 u = ((const float2*)(g_acc + (size_t)ur * D))[lane];
    float2 v = ((const float2*)(g_acc + (size_t)ir * D))[lane];
    float s = u.x * v.x + u.y * v.y;
    #pragma unroll
    for (int o = 16; o; o >>= 1) s += __shfl_xor_sync(0xffffffffu, s, o);
    if (lane == 0) out[pair] = s * (1.0f / 16.0f);
}

extern "C" void kernel_launch(void* const* d_in, const int* in_sizes, int n_in,
                              void* d_out, int out_size) {
    const float* ue    = (const float*)d_in[0];
    const float* ie    = (const float*)d_in[1];
    const int*   esrc  = (const int*)  d_in[2];
    const int*   edst  = (const int*)  d_in[3];
    const float* ew    = (const float*)d_in[4];
    const int*   users = (const int*)  d_in[5];
    const int*   items = (const int*)  d_in[6];

    int n_user_f  = in_sizes[0];
    int n_item_f  = in_sizes[1];
    int n_edges   = in_sizes[2];
    int B         = in_sizes[5];
    int n_total_f = n_user_f + n_item_f;
    int n_users   = n_user_f / D;
    int n4        = n_total_f >> 2;

    init_kernel<<<(n4 + 255) / 256, 256>>>(ue, ie, n_user_f, n4);

    for (int l = 0; l < 3; l++) {
        int flip = l & 1;
        long long t = (long long)n_edges * 16;
        spmm_kernel<<<(int)((t + 255) / 256), 256>>>(esrc, edst, ew, n_edges, flip);
        addclear_kernel<<<(n4 + 255) / 256, 256>>>(n4, flip);
    }

    score_kernel<<<(B * 32 + 255) / 256, 256>>>(users, items, (float*)d_out,
                                                B, n_users);
}